// round 11
// baseline (speedup 1.0000x reference)
#include <cuda_runtime.h>
#include <cuda_fp16.h>

#define CCH 256        // channels (all levels)
#define NIMG 2         // batch
#define NBINS 49       // 7*7
#define SPITCH 260     // staging pitch in floats (CCH+4): 16B-aligned

// NHWC fp16 scratch for all 4 levels (element offsets):
// L0 @ 0, L1 @ 33,554,432, L2 @ 41,943,040, L3 @ 44,040,192 (89 MB total)
__device__ __half g_nhwc[44564480];

__constant__ long long c_lvl_off[4] = {0LL, 33554432LL, 41943040LL, 44040192LL};

// ---------------------------------------------------------------------------
// Fused NCHW(fp32) -> NHWC(fp16) transpose, 4 hw-subtiles per CTA (MLP=4).
// blockIdx.x: L0 [0,512), L1 [512,640), L2 [640,672), L3 [672,680).
// blockIdx.y = channel tile (8), blockIdx.z = image (2). Block (8,32).
// (R7/R8 version — measured ~6.1 TB/s effective, at the streaming cap.)
// ---------------------------------------------------------------------------
__global__ __launch_bounds__(256) void transpose_fused(
    const float* __restrict__ f0, const float* __restrict__ f1,
    const float* __restrict__ f2, const float* __restrict__ f3)
{
    __shared__ float tile[4][32][33];              // 16,896 B

    const int bx = blockIdx.x;
    int lvl, tb;
    const float* src;
    if (bx < 512)      { lvl = 0; tb = bx;       src = f0; }
    else if (bx < 640) { lvl = 1; tb = bx - 512; src = f1; }
    else if (bx < 672) { lvl = 2; tb = bx - 640; src = f2; }
    else               { lvl = 3; tb = bx - 672; src = f3; }

    const int HW  = (256 >> lvl) * (256 >> lvl);
    const int hw0 = tb * 128;
    const int c0  = blockIdx.y * 32;
    const int n   = blockIdx.z;
    const int tx  = threadIdx.x;   // 0..7
    const int ty  = threadIdx.y;   // 0..31

    const float* s = src + (size_t)n * CCH * HW + (size_t)(c0 + ty) * HW + hw0 + tx * 4;

#pragma unroll
    for (int j = 0; j < 4; ++j) {
        const float4 v = *reinterpret_cast<const float4*>(s + j * 32);
        tile[j][ty][tx * 4 + 0] = v.x;
        tile[j][ty][tx * 4 + 1] = v.y;
        tile[j][ty][tx * 4 + 2] = v.z;
        tile[j][ty][tx * 4 + 3] = v.w;
    }
    __syncthreads();

    __half* dst = g_nhwc + c_lvl_off[lvl] + (size_t)n * HW * CCH
                + (size_t)(hw0 + ty) * CCH + c0 + tx * 4;

#pragma unroll
    for (int j = 0; j < 4; ++j) {
        const __half2 a = __floats2half2_rn(tile[j][tx * 4 + 0][ty], tile[j][tx * 4 + 1][ty]);
        const __half2 b = __floats2half2_rn(tile[j][tx * 4 + 2][ty], tile[j][tx * 4 + 3][ty]);
        uint2 o;
        o.x = *reinterpret_cast<const unsigned int*>(&a);
        o.y = *reinterpret_cast<const unsigned int*>(&b);
        *reinterpret_cast<uint2*>(dst + (size_t)j * 32 * CCH) = o;
    }
}

// ---------------------------------------------------------------------------
// ROIAlign pooler over fp16 NHWC scratch. TWO CTAs per box (phase 0: bins
// [0,25), phase 1: [25,49)). 256 threads: q = tid&31 -> channel oct (uint4
// of 8 halves); bs = tid>>5 -> bin (one bin per warp per iteration).
//
// SEPARABLE TAP DEDUP: per bin and axis, the 4 taps (2 samples x 2 corners)
// are merged into <=4 unique coordinates with summed weights (zero-weight
// taps dropped). Bin value = sum_yi sum_xi Wy[yi]*Wx[xi]*V[y,x] -- identical
// arithmetic to the 16-tap form, ~30% fewer LDG and ~50% fewer table LDS.
// fp16 x-axis combine (<=4-term HFMA2 chain), fp32 y-weight accumulation.
// ---------------------------------------------------------------------------
__global__ __launch_bounds__(256) void roi_pool_kernel(
    const float* __restrict__ boxes, float* __restrict__ out, int R)
{
    __shared__ float s_out[25 * SPITCH];           // 26,000 B
    __shared__ int   s_yoff[25][4];                // unique y offsets (pre-multiplied by Wd)
    __shared__ float s_ywt[25][4];                 // y weights (x0.25 folded, fp32)
    __shared__ int   s_xoff[25][4];                // unique x offsets
    __shared__ unsigned int s_xwt[25][4];          // x weights as broadcast half2
    __shared__ int   s_cnt[25];                    // ny | (nx<<8)
    __shared__ int   s_i0[2][14], s_i1[2][14];
    __shared__ float s_h[2][14],  s_l[2][14];

    const int bid   = blockIdx.x;
    const int m     = bid >> 1;
    const int phase = bid & 1;
    const int tid   = threadIdx.x;

    const int b0   = phase ? 25 : 0;
    const int bcnt = phase ? 24 : 25;

    const float bx1 = __ldg(boxes + 4 * m + 0);
    const float by1 = __ldg(boxes + 4 * m + 1);
    const float bx2 = __ldg(boxes + 4 * m + 2);
    const float by2 = __ldg(boxes + 4 * m + 3);

    const float area = fmaxf((bx2 - bx1) * (by2 - by1), 0.0f);
    const float sz   = sqrtf(area);
    int lvl = (int)floorf(4.0f + log2f(sz / 224.0f + 1e-8f));
    lvl = min(max(lvl, 2), 5) - 2;                 // 0..3

    const int   Hd    = 256 >> lvl;
    const int   Wd    = Hd;
    const float scale = 0.25f / (float)(1 << lvl);
    const int   n     = m / R;

    const __half* fbase = g_nhwc + c_lvl_off[lvl] + (size_t)n * Hd * Wd * CCH;

    if (tid < 28) {
        const int axis = tid / 14;                 // 0 = x, 1 = y
        const int k    = tid - axis * 14;
        const float c1 = axis ? by1 : bx1;
        const float c2 = axis ? by2 : bx2;
        const int  lim = Hd;
        const float start = c1 * scale - 0.5f;
        const float bsz   = (c2 * scale - 0.5f - start) * (1.0f / 7.0f);
        const float off   = (float)(k >> 1) + ((k & 1) ? 0.75f : 0.25f);
        const float t     = start + off * bsz;
        const bool  v     = (t >= -1.0f) && (t <= (float)lim);
        const float tc    = fminf(fmaxf(t, 0.0f), (float)(lim - 1));
        const int   i0    = (int)tc;
        const int   i1    = min(i0 + 1, lim - 1);
        const float l     = tc - (float)i0;
        s_i0[axis][k] = i0;
        s_i1[axis][k] = i1;
        s_l[axis][k]  = v ? l : 0.0f;
        s_h[axis][k]  = v ? (1.0f - l) : 0.0f;
    }
    __syncthreads();

    // Per-bin separable dedup table build (one thread per local bin).
    if (tid < bcnt) {
        const int bin = b0 + tid;
        const int py  = bin / 7;
        const int px  = bin - py * 7;

        int   cc[2][4];
        float cw[2][4];
        int   cn[2] = {0, 0};
#pragma unroll
        for (int axis = 0; axis < 2; ++axis) {
            const int base = (axis ? py : px) * 2;
#pragma unroll
            for (int t = 0; t < 4; ++t) {          // t: sample(1b)<<1 | corner(1b)
                const int   k = base + (t >> 1);
                const int   c = (t & 1) ? s_i1[axis][k] : s_i0[axis][k];
                const float w = (t & 1) ? s_l[axis][k]  : s_h[axis][k];
                if (w != 0.0f) {
                    int j = 0;
                    for (; j < cn[axis]; ++j)
                        if (cc[axis][j] == c) { cw[axis][j] += w; break; }
                    if (j == cn[axis]) {
                        cc[axis][j] = c;
                        cw[axis][j] = w;
                        cn[axis]++;
                    }
                }
            }
        }
#pragma unroll
        for (int j = 0; j < 4; ++j) {
            const int jy = (j < cn[1]) ? j : 0;
            const int jx = (j < cn[0]) ? j : 0;
            s_yoff[tid][j] = cc[1][jy] * Wd;
            s_ywt[tid][j]  = (j < cn[1]) ? cw[1][jy] * 0.25f : 0.0f;
            s_xoff[tid][j] = cc[0][jx];
            const __half2 hw = __float2half2_rn((j < cn[0]) ? cw[0][jx] : 0.0f);
            s_xwt[tid][j] = *reinterpret_cast<const unsigned int*>(&hw);
        }
        s_cnt[tid] = cn[1] | (cn[0] << 8);
    }
    __syncthreads();

    const int q  = tid & 31;
    const int bs = tid >> 5;
    const uint4* base16 = reinterpret_cast<const uint4*>(fbase) + q;
    float* outm = out + (size_t)m * (NBINS * CCH);

    for (int bb = bs; bb < bcnt; bb += 8) {
        const int cnt = s_cnt[bb];
        const int ny  = cnt & 255;
        const int nx  = cnt >> 8;
        float2 facc[4] = {{0.f,0.f},{0.f,0.f},{0.f,0.f},{0.f,0.f}};

        for (int yi = 0; yi < ny; ++yi) {
            const int   yo = s_yoff[bb][yi];
            const float wy = s_ywt[bb][yi];
            __half2 hacc[4] = {__half2(0.f,0.f), __half2(0.f,0.f),
                               __half2(0.f,0.f), __half2(0.f,0.f)};
#pragma unroll 4
            for (int xi = 0; xi < nx; ++xi) {
                const unsigned int wb = s_xwt[bb][xi];
                const __half2 w = *reinterpret_cast<const __half2*>(&wb);
                const uint4 u = __ldg(base16 + (size_t)(yo + s_xoff[bb][xi]) * 32);
                const __half2* h = reinterpret_cast<const __half2*>(&u);
#pragma unroll
                for (int j = 0; j < 4; ++j)
                    hacc[j] = __hfma2(h[j], w, hacc[j]);
            }
#pragma unroll
            for (int j = 0; j < 4; ++j) {
                const float2 f = __half22float2(hacc[j]);
                facc[j].x += wy * f.x;
                facc[j].y += wy * f.y;
            }
        }
        float4* s4 = reinterpret_cast<float4*>(s_out + bb * SPITCH + q * 8);
        s4[0] = make_float4(facc[0].x, facc[0].y, facc[1].x, facc[1].y);
        s4[1] = make_float4(facc[2].x, facc[2].y, facc[3].x, facc[3].y);
    }
    __syncthreads();

    // Transposed dump: compile-time bin counts (magic-multiply div).
    if (phase == 0) {
        for (int i = tid; i < 25 * CCH; i += 256) {
            const int c  = i / 25;
            const int bb = i - c * 25;
            outm[c * NBINS + bb] = s_out[bb * SPITCH + c];
        }
    } else {
        for (int i = tid; i < 24 * CCH; i += 256) {
            const int c  = i / 24;
            const int bb = i - c * 24;
            outm[c * NBINS + 25 + bb] = s_out[bb * SPITCH + c];
        }
    }
}

// ---------------------------------------------------------------------------
extern "C" void kernel_launch(void* const* d_in, const int* in_sizes, int n_in,
                              void* d_out, int out_size)
{
    const float* f0    = (const float*)d_in[0];
    const float* f1    = (const float*)d_in[1];
    const float* f2    = (const float*)d_in[2];
    const float* f3    = (const float*)d_in[3];
    const float* boxes = (const float*)d_in[4];
    float*       out   = (float*)d_out;

    const int M = in_sizes[4] / 4;   // 1024 boxes
    const int R = M / NIMG;          // 512 per image

    transpose_fused<<<dim3(680, CCH / 32, NIMG), dim3(8, 32)>>>(f0, f1, f2, f3);
    roi_pool_kernel<<<M * 2, 256>>>(boxes, out, R);
}

// round 12
// speedup vs baseline: 1.0489x; 1.0489x over previous
#include <cuda_runtime.h>
#include <cuda_fp16.h>

#define CCH 256        // channels (all levels)
#define NIMG 2         // batch
#define NBINS 49       // 7*7
#define SPITCH 260     // staging pitch in floats (CCH+4): 16B-aligned

// NHWC fp16 scratch for all 4 levels (element offsets):
// L0 @ 0, L1 @ 33,554,432, L2 @ 41,943,040, L3 @ 44,040,192 (89 MB total)
__device__ __half g_nhwc[44564480];

__constant__ long long c_lvl_off[4] = {0LL, 33554432LL, 41943040LL, 44040192LL};

// ---------------------------------------------------------------------------
// Fused NCHW(fp32) -> NHWC(fp16) transpose, 4 hw-subtiles per CTA (MLP=4).
// blockIdx.x: L0 [0,512), L1 [512,640), L2 [640,672), L3 [672,680).
// blockIdx.y = channel tile (8), blockIdx.z = image (2). Block (8,32).
// (R8 version — measured ~6.1 TB/s effective, at the streaming cap.)
// ---------------------------------------------------------------------------
__global__ __launch_bounds__(256) void transpose_fused(
    const float* __restrict__ f0, const float* __restrict__ f1,
    const float* __restrict__ f2, const float* __restrict__ f3)
{
    __shared__ float tile[4][32][33];              // 16,896 B

    const int bx = blockIdx.x;
    int lvl, tb;
    const float* src;
    if (bx < 512)      { lvl = 0; tb = bx;       src = f0; }
    else if (bx < 640) { lvl = 1; tb = bx - 512; src = f1; }
    else if (bx < 672) { lvl = 2; tb = bx - 640; src = f2; }
    else               { lvl = 3; tb = bx - 672; src = f3; }

    const int HW  = (256 >> lvl) * (256 >> lvl);
    const int hw0 = tb * 128;
    const int c0  = blockIdx.y * 32;
    const int n   = blockIdx.z;
    const int tx  = threadIdx.x;   // 0..7
    const int ty  = threadIdx.y;   // 0..31

    const float* s = src + (size_t)n * CCH * HW + (size_t)(c0 + ty) * HW + hw0 + tx * 4;

#pragma unroll
    for (int j = 0; j < 4; ++j) {
        const float4 v = *reinterpret_cast<const float4*>(s + j * 32);
        tile[j][ty][tx * 4 + 0] = v.x;
        tile[j][ty][tx * 4 + 1] = v.y;
        tile[j][ty][tx * 4 + 2] = v.z;
        tile[j][ty][tx * 4 + 3] = v.w;
    }
    __syncthreads();

    __half* dst = g_nhwc + c_lvl_off[lvl] + (size_t)n * HW * CCH
                + (size_t)(hw0 + ty) * CCH + c0 + tx * 4;

#pragma unroll
    for (int j = 0; j < 4; ++j) {
        const __half2 a = __floats2half2_rn(tile[j][tx * 4 + 0][ty], tile[j][tx * 4 + 1][ty]);
        const __half2 b = __floats2half2_rn(tile[j][tx * 4 + 2][ty], tile[j][tx * 4 + 3][ty]);
        uint2 o;
        o.x = *reinterpret_cast<const unsigned int*>(&a);
        o.y = *reinterpret_cast<const unsigned int*>(&b);
        *reinterpret_cast<uint2*>(dst + (size_t)j * 32 * CCH) = o;
    }
}

// ---------------------------------------------------------------------------
// ROIAlign pooler over fp16 NHWC scratch. TWO CTAs per box (phase 0: bins
// [0,25), phase 1: [25,49)). 256 threads: q = tid&31 -> channel oct (uint4
// of 8 halves); bs = tid>>5 -> bin (one bin per warp per iteration).
//
// DEDUPED FLAT TAP LIST (static inner structure): per bin, the 16 bilinear
// taps are merged by unique pixel (per-axis unique coords <=4, weights
// summed; zero-weight taps dropped) into ntap <= 16 entries, PADDED to a
// multiple of 4 with zero-weight taps. Compute loops over groups of 4 taps:
// 4 batched LDG.128 + length-4 fp16 HFMA2 chain + one fp32 convert/add per
// group — identical issue pattern to R8, ~20% fewer loads.
// ---------------------------------------------------------------------------
__global__ __launch_bounds__(256) void roi_pool_kernel(
    const float* __restrict__ boxes, float* __restrict__ out, int R)
{
    __shared__ float s_out[25 * SPITCH];           // 26,000 B
    __shared__ uint2 s_tap[25 * 16];               //  3,200 B {offset, half2 w}
    __shared__ int   s_ntap[25];                   // padded tap count (mult of 4)
    __shared__ int   s_i0[2][14], s_i1[2][14];
    __shared__ float s_h[2][14],  s_l[2][14];

    const int bid   = blockIdx.x;
    const int m     = bid >> 1;
    const int phase = bid & 1;
    const int tid   = threadIdx.x;

    const int b0   = phase ? 25 : 0;
    const int bcnt = phase ? 24 : 25;

    const float bx1 = __ldg(boxes + 4 * m + 0);
    const float by1 = __ldg(boxes + 4 * m + 1);
    const float bx2 = __ldg(boxes + 4 * m + 2);
    const float by2 = __ldg(boxes + 4 * m + 3);

    const float area = fmaxf((bx2 - bx1) * (by2 - by1), 0.0f);
    const float sz   = sqrtf(area);
    int lvl = (int)floorf(4.0f + log2f(sz / 224.0f + 1e-8f));
    lvl = min(max(lvl, 2), 5) - 2;                 // 0..3

    const int   Hd    = 256 >> lvl;
    const int   Wd    = Hd;
    const float scale = 0.25f / (float)(1 << lvl);
    const int   n     = m / R;

    const __half* fbase = g_nhwc + c_lvl_off[lvl] + (size_t)n * Hd * Wd * CCH;

    if (tid < 28) {
        const int axis = tid / 14;                 // 0 = x, 1 = y
        const int k    = tid - axis * 14;
        const float c1 = axis ? by1 : bx1;
        const float c2 = axis ? by2 : bx2;
        const int  lim = Hd;
        const float start = c1 * scale - 0.5f;
        const float bsz   = (c2 * scale - 0.5f - start) * (1.0f / 7.0f);
        const float off   = (float)(k >> 1) + ((k & 1) ? 0.75f : 0.25f);
        const float t     = start + off * bsz;
        const bool  v     = (t >= -1.0f) && (t <= (float)lim);
        const float tc    = fminf(fmaxf(t, 0.0f), (float)(lim - 1));
        const int   i0    = (int)tc;
        const int   i1    = min(i0 + 1, lim - 1);
        const float l     = tc - (float)i0;
        s_i0[axis][k] = i0;
        s_i1[axis][k] = i1;
        s_l[axis][k]  = v ? l : 0.0f;
        s_h[axis][k]  = v ? (1.0f - l) : 0.0f;
    }
    __syncthreads();

    // Deduped tap-list build: one thread per local bin.
    if (tid < bcnt) {
        const int bin = b0 + tid;
        const int py  = bin / 7;
        const int px  = bin - py * 7;

        int   cc[2][4];
        float cw[2][4];
        int   cn[2] = {0, 0};
#pragma unroll
        for (int axis = 0; axis < 2; ++axis) {
            const int base = (axis ? py : px) * 2;
#pragma unroll
            for (int t = 0; t < 4; ++t) {          // t = sample(1b)<<1 | corner(1b)
                const int   k = base + (t >> 1);
                const int   c = (t & 1) ? s_i1[axis][k] : s_i0[axis][k];
                const float w = (t & 1) ? s_l[axis][k]  : s_h[axis][k];
                if (w != 0.0f) {
                    int j = 0;
                    for (; j < cn[axis]; ++j)
                        if (cc[axis][j] == c) { cw[axis][j] += w; break; }
                    if (j == cn[axis]) { cc[axis][j] = c; cw[axis][j] = w; cn[axis]++; }
                }
            }
        }

        const int tbase = tid * 16;
        int ntap = 0;
        for (int yi = 0; yi < cn[1]; ++yi) {
            const int   yo = cc[1][yi] * Wd;
            const float wy = cw[1][yi] * 0.25f;
            for (int xi = 0; xi < cn[0]; ++xi) {
                const __half2 hw = __float2half2_rn(wy * cw[0][xi]);
                uint2 e;
                e.x = (unsigned int)(yo + cc[0][xi]);
                e.y = *reinterpret_cast<const unsigned int*>(&hw);
                s_tap[tbase + ntap++] = e;
            }
        }
        // pad to multiple of 4 with zero-weight copies of tap 0
        if (ntap > 0) {
            uint2 pad = s_tap[tbase];
            pad.y = 0u;                            // half2(0,0)
            while (ntap & 3) s_tap[tbase + ntap++] = pad;
        }
        s_ntap[tid] = ntap;
    }
    __syncthreads();

    const int q  = tid & 31;
    const int bs = tid >> 5;
    const uint4* base16 = reinterpret_cast<const uint4*>(fbase) + q;
    float* outm = out + (size_t)m * (NBINS * CCH);

    for (int bb = bs; bb < bcnt; bb += 8) {
        const int ntap = s_ntap[bb];
        const int tb   = bb * 16;
        float2 facc[4] = {{0.f,0.f},{0.f,0.f},{0.f,0.f},{0.f,0.f}};

        for (int t0 = 0; t0 < ntap; t0 += 4) {
            __half2 hacc[4];
#pragma unroll
            for (int t = 0; t < 4; ++t) {
                const uint2 e = s_tap[tb + t0 + t];            // LDS.64 broadcast
                const __half2 w = *reinterpret_cast<const __half2*>(&e.y);
                const uint4 u = __ldg(base16 + (size_t)e.x * 32);
                const __half2* h = reinterpret_cast<const __half2*>(&u);
#pragma unroll
                for (int j = 0; j < 4; ++j)
                    hacc[j] = (t == 0) ? __hmul2(h[j], w)
                                       : __hfma2(h[j], w, hacc[j]);
            }
#pragma unroll
            for (int j = 0; j < 4; ++j) {
                const float2 f = __half22float2(hacc[j]);
                facc[j].x += f.x;
                facc[j].y += f.y;
            }
        }
        float4* s4 = reinterpret_cast<float4*>(s_out + bb * SPITCH + q * 8);
        s4[0] = make_float4(facc[0].x, facc[0].y, facc[1].x, facc[1].y);
        s4[1] = make_float4(facc[2].x, facc[2].y, facc[3].x, facc[3].y);
    }
    __syncthreads();

    // Transposed dump: compile-time bin counts (magic-multiply div).
    if (phase == 0) {
        for (int i = tid; i < 25 * CCH; i += 256) {
            const int c  = i / 25;
            const int bb = i - c * 25;
            outm[c * NBINS + bb] = s_out[bb * SPITCH + c];
        }
    } else {
        for (int i = tid; i < 24 * CCH; i += 256) {
            const int c  = i / 24;
            const int bb = i - c * 24;
            outm[c * NBINS + 25 + bb] = s_out[bb * SPITCH + c];
        }
    }
}

// ---------------------------------------------------------------------------
extern "C" void kernel_launch(void* const* d_in, const int* in_sizes, int n_in,
                              void* d_out, int out_size)
{
    const float* f0    = (const float*)d_in[0];
    const float* f1    = (const float*)d_in[1];
    const float* f2    = (const float*)d_in[2];
    const float* f3    = (const float*)d_in[3];
    const float* boxes = (const float*)d_in[4];
    float*       out   = (float*)d_out;

    const int M = in_sizes[4] / 4;   // 1024 boxes
    const int R = M / NIMG;          // 512 per image

    transpose_fused<<<dim3(680, CCH / 32, NIMG), dim3(8, 32)>>>(f0, f1, f2, f3);
    roi_pool_kernel<<<M * 2, 256>>>(boxes, out, R);
}